// round 3
// baseline (speedup 1.0000x reference)
#include <cuda_runtime.h>
#include <math.h>

#define NUM_TASKS 1000
#define NF 256
#define NH 128
#define BATCH 4096
#define CHUNK 8

// Scratch (no allocations allowed) — grouping metadata
__device__ int g_count[NUM_TASKS];
__device__ int g_off[NUM_TASKS + 1];
__device__ int g_cursor[NUM_TASKS];
__device__ int g_order[BATCH];

__global__ void zero_counts_k() {
    int i = blockIdx.x * blockDim.x + threadIdx.x;
    if (i < NUM_TASKS) g_count[i] = 0;
}

__global__ void count_k(const int* __restrict__ task_ids, int n) {
    int i = blockIdx.x * blockDim.x + threadIdx.x;
    if (i < n) atomicAdd(&g_count[task_ids[i]], 1);
}

// Single-block Hillis-Steele scan over 1000 counts (1024 threads)
__global__ void scan_k() {
    __shared__ int s[1024];
    int i = threadIdx.x;
    s[i] = (i < NUM_TASKS) ? g_count[i] : 0;
    __syncthreads();
    for (int d = 1; d < 1024; d <<= 1) {
        int v = 0;
        if (i >= d) v = s[i - d];
        __syncthreads();
        s[i] += v;
        __syncthreads();
    }
    if (i < NUM_TASKS) {
        g_off[i + 1] = s[i];                  // inclusive -> exclusive shifted
        int start = (i == 0) ? 0 : s[i - 1];
        g_cursor[i] = start;
        if (i == 0) g_off[0] = 0;
    }
}

__global__ void scatter_k(const int* __restrict__ task_ids, int n) {
    int i = blockIdx.x * blockDim.x + threadIdx.x;
    if (i < n) {
        int p = atomicAdd(&g_cursor[task_ids[i]], 1);
        g_order[p] = i;
    }
}

__device__ __forceinline__ float gelu_exact(float h) {
    return 0.5f * h * (1.0f + erff(h * 0.70710678118654752f));
}

// One CTA per task. 128 threads = hidden columns. Stream W1 once per chunk of
// up to 8 samples (~97% of tasks => exactly one W1 pass). x rows staged in smem.
__global__ __launch_bounds__(128) void mlp_k(
    const float* __restrict__ x,
    const float* __restrict__ l1_emb,
    const float* __restrict__ l1_bias,
    const float* __restrict__ l2_emb,
    const float* __restrict__ l2_bias,
    float* __restrict__ out)
{
    int t = blockIdx.x;
    int beg = g_off[t];
    int n   = g_off[t + 1] - beg;
    if (n == 0) return;

    int j    = threadIdx.x;        // hidden column 0..127
    int lane = j & 31;
    int wid  = j >> 5;

    const float* __restrict__ W = l1_emb + (size_t)t * (NF * NH);
    float b1 = l1_bias[t * NH + j];
    float w2 = l2_emb[t * NH + j];
    float b2 = l2_bias[t];

    __shared__ float sx[CHUNK][NF];     // 8 KB
    __shared__ int   sidx[CHUNK];
    __shared__ float sred[4][CHUNK];    // 4 warps x CHUNK samples

    for (int s0 = 0; s0 < n; s0 += CHUNK) {
        int S = min(CHUNK, n - s0);

        // Stage x rows. Pad slots (s >= S) replicate the chunk's first sample;
        // they are computed but never stored (guarded by j < S below).
        #pragma unroll
        for (int s = 0; s < CHUNK; s++) {
            int src = beg + s0 + ((s < S) ? s : 0);
            int ord = __ldg(&g_order[src]);
            if (j == s) sidx[s] = ord;
            const float* xr = x + (size_t)ord * NF;
            sx[s][j]       = xr[j];
            sx[s][j + 128] = xr[j + 128];
        }
        __syncthreads();

        float acc[CHUNK];
        #pragma unroll
        for (int s = 0; s < CHUNK; s++) acc[s] = 0.f;

        #pragma unroll 2
        for (int fq = 0; fq < NF / 4; fq++) {
            int f = fq * 4;
            float w_0 = W[(f + 0) * NH + j];
            float w_1 = W[(f + 1) * NH + j];
            float w_2 = W[(f + 2) * NH + j];
            float w_3 = W[(f + 3) * NH + j];
            #pragma unroll
            for (int s = 0; s < CHUNK; s++) {
                float4 xv = ((const float4*)sx[s])[fq];
                acc[s] += xv.x * w_0 + xv.y * w_1 + xv.z * w_2 + xv.w * w_3;
            }
        }

        // Layer 2: gelu(h)*w2, reduce over 128 columns per sample
        #pragma unroll
        for (int s = 0; s < CHUNK; s++) {
            float v = gelu_exact(acc[s] + b1) * w2;
            v += __shfl_xor_sync(0xffffffff, v, 16);
            v += __shfl_xor_sync(0xffffffff, v, 8);
            v += __shfl_xor_sync(0xffffffff, v, 4);
            v += __shfl_xor_sync(0xffffffff, v, 2);
            v += __shfl_xor_sync(0xffffffff, v, 1);
            if (lane == 0) sred[wid][s] = v;
        }
        __syncthreads();

        if (j < S) {
            float sum = sred[0][j] + sred[1][j] + sred[2][j] + sred[3][j];
            out[sidx[j]] = sum + b2;
        }
        __syncthreads();   // protect sx/sred before next chunk
    }
}

extern "C" void kernel_launch(void* const* d_in, const int* in_sizes, int n_in,
                              void* d_out, int out_size) {
    const float* x       = (const float*)d_in[0];
    const int*   task_id = (const int*)  d_in[1];
    const float* l1_emb  = (const float*)d_in[2];
    const float* l1_bias = (const float*)d_in[3];
    const float* l2_emb  = (const float*)d_in[4];
    const float* l2_bias = (const float*)d_in[5];
    float* out = (float*)d_out;

    int nb = in_sizes[1];  // BATCH

    zero_counts_k<<<(NUM_TASKS + 255) / 256, 256>>>();
    count_k<<<(nb + 255) / 256, 256>>>(task_id, nb);
    scan_k<<<1, 1024>>>();
    scatter_k<<<(nb + 255) / 256, 256>>>(task_id, nb);
    mlp_k<<<NUM_TASKS, 128>>>(x, l1_emb, l1_bias, l2_emb, l2_bias, out);
}

// round 5
// speedup vs baseline: 1.1964x; 1.1964x over previous
#include <cuda_runtime.h>
#include <math.h>

#define NUM_TASKS 1000
#define NF 256
#define NH 128
#define BATCH 4096

// Scratch (no allocations allowed) — grouping metadata
__device__ int g_off[NUM_TASKS + 1];
__device__ int g_order[BATCH];

// ---------------------------------------------------------------------------
// Fused prep: count + scan + scatter in ONE single-block kernel.
// 4096 elements, 1000 bins — trivial work, one launch instead of four.
// ---------------------------------------------------------------------------
__global__ __launch_bounds__(1024) void prep_k(const int* __restrict__ task_ids, int n) {
    __shared__ int cnt[NUM_TASKS];     // counts, then reused as cursors
    __shared__ int sc[1024];
    int tid = threadIdx.x;

    for (int i = tid; i < NUM_TASKS; i += 1024) cnt[i] = 0;
    __syncthreads();

    for (int i = tid; i < n; i += 1024) atomicAdd(&cnt[task_ids[i]], 1);
    __syncthreads();

    // Hillis-Steele inclusive scan over 1024 slots
    sc[tid] = (tid < NUM_TASKS) ? cnt[tid] : 0;
    __syncthreads();
    for (int d = 1; d < 1024; d <<= 1) {
        int v = (tid >= d) ? sc[tid - d] : 0;
        __syncthreads();
        sc[tid] += v;
        __syncthreads();
    }
    if (tid < NUM_TASKS) {
        g_off[tid + 1] = sc[tid];
        if (tid == 0) g_off[0] = 0;
        cnt[tid] = (tid == 0) ? 0 : sc[tid - 1];   // cursor = exclusive start
    }
    __syncthreads();

    for (int i = tid; i < n; i += 1024) {
        int p = atomicAdd(&cnt[task_ids[i]], 1);
        g_order[p] = i;
    }
}

__device__ __forceinline__ float gelu_exact(float h) {
    return 0.5f * h * (1.0f + erff(h * 0.70710678118654752f));
}

// ---------------------------------------------------------------------------
// Chunk body specialized on SS (compile-time samples-in-flight).
// S = actual live samples (<= SS); pad slots replicate sample 0 and are
// computed but never stored.
// ---------------------------------------------------------------------------
template<int SS>
__device__ __forceinline__ void do_chunk(
    int base, int S, int j, int lane, int wid,
    const float* __restrict__ x, const float* __restrict__ W,
    float b1, float w2, float b2,
    float (*sx)[NF], int* sidx, float (*sred)[8],
    float* __restrict__ out)
{
    #pragma unroll
    for (int s = 0; s < SS; s++) {
        int src = base + ((s < S) ? s : 0);
        int ord = __ldg(&g_order[src]);
        if (j == s) sidx[s] = ord;
        const float* xr = x + (size_t)ord * NF;
        sx[s][j]       = xr[j];
        sx[s][j + 128] = xr[j + 128];
    }
    __syncthreads();

    float acc[SS];
    #pragma unroll
    for (int s = 0; s < SS; s++) acc[s] = 0.f;

    #pragma unroll 2
    for (int fq = 0; fq < NF / 4; fq++) {
        int f = fq * 4;
        float w_0 = W[(f + 0) * NH + j];
        float w_1 = W[(f + 1) * NH + j];
        float w_2 = W[(f + 2) * NH + j];
        float w_3 = W[(f + 3) * NH + j];
        #pragma unroll
        for (int s = 0; s < SS; s++) {
            float4 xv = ((const float4*)sx[s])[fq];
            acc[s] += xv.x * w_0 + xv.y * w_1 + xv.z * w_2 + xv.w * w_3;
        }
    }

    #pragma unroll
    for (int s = 0; s < SS; s++) {
        float v = gelu_exact(acc[s] + b1) * w2;
        v += __shfl_xor_sync(0xffffffff, v, 16);
        v += __shfl_xor_sync(0xffffffff, v, 8);
        v += __shfl_xor_sync(0xffffffff, v, 4);
        v += __shfl_xor_sync(0xffffffff, v, 2);
        v += __shfl_xor_sync(0xffffffff, v, 1);
        if (lane == 0) sred[wid][s] = v;
    }
    __syncthreads();

    if (j < S) {
        float sum = sred[0][j] + sred[1][j] + sred[2][j] + sred[3][j];
        out[sidx[j]] = sum + b2;
    }
    __syncthreads();   // protect sx/sred before any next chunk
}

// One CTA per task. 128 threads = hidden columns. Stream W1 once per chunk;
// chunk width specialized to {2,4,8} to avoid pad-slot compute waste.
__global__ __launch_bounds__(128) void mlp_k(
    const float* __restrict__ x,
    const float* __restrict__ l1_emb,
    const float* __restrict__ l1_bias,
    const float* __restrict__ l2_emb,
    const float* __restrict__ l2_bias,
    float* __restrict__ out)
{
    int t = blockIdx.x;
    int beg = g_off[t];
    int n   = g_off[t + 1] - beg;
    if (n == 0) return;

    int j    = threadIdx.x;
    int lane = j & 31;
    int wid  = j >> 5;

    const float* __restrict__ W = l1_emb + (size_t)t * (NF * NH);
    float b1 = l1_bias[t * NH + j];
    float w2 = l2_emb[t * NH + j];
    float b2 = l2_bias[t];

    __shared__ float sx[8][NF];     // 8 KB
    __shared__ int   sidx[8];
    __shared__ float sred[4][8];

    int pos = beg, rem = n;
    while (rem > 0) {
        if (rem > 4) {
            do_chunk<8>(pos, min(rem, 8), j, lane, wid, x, W, b1, w2, b2, sx, sidx, sred, out);
            pos += 8; rem -= 8;
        } else if (rem > 2) {
            do_chunk<4>(pos, rem, j, lane, wid, x, W, b1, w2, b2, sx, sidx, sred, out);
            rem = 0;
        } else {
            do_chunk<2>(pos, rem, j, lane, wid, x, W, b1, w2, b2, sx, sidx, sred, out);
            rem = 0;
        }
    }
}

extern "C" void kernel_launch(void* const* d_in, const int* in_sizes, int n_in,
                              void* d_out, int out_size) {
    const float* x       = (const float*)d_in[0];
    const int*   task_id = (const int*)  d_in[1];
    const float* l1_emb  = (const float*)d_in[2];
    const float* l1_bias = (const float*)d_in[3];
    const float* l2_emb  = (const float*)d_in[4];
    const float* l2_bias = (const float*)d_in[5];
    float* out = (float*)d_out;

    int nb = in_sizes[1];  // BATCH

    prep_k<<<1, 1024>>>(task_id, nb);
    mlp_k<<<NUM_TASKS, 128>>>(x, l1_emb, l1_bias, l2_emb, l2_bias, out);
}